// round 4
// baseline (speedup 1.0000x reference)
#include <cuda_runtime.h>

#define H_ 4
#define D_ 64
#define L_ 7
#define VOCAB_ 6
#define NOUT_ 11
#define BATCH_ 32768
#define EPS_ 1e-5f

using u64 = unsigned long long;

// ---- packed f32x2 helpers (sm_100+) ----
__device__ __forceinline__ u64 pk2(float x, float y) {
    u64 r; asm("mov.b64 %0, {%1, %2};" : "=l"(r) : "f"(x), "f"(y)); return r;
}
__device__ __forceinline__ u64 bc2(float x) {
    u64 r; asm("mov.b64 %0, {%1, %1};" : "=l"(r) : "f"(x)); return r;
}
__device__ __forceinline__ void fma2(u64& a, u64 x, u64 w) {
    asm("fma.rn.f32x2 %0, %1, %2, %0;" : "+l"(a) : "l"(x), "l"(w));
}
__device__ __forceinline__ float2 up2(u64 v) {
    float2 r; asm("mov.b64 {%0, %1}, %2;" : "=f"(r.x), "=f"(r.y) : "l"(v)); return r;
}

// ---------------- scratch (no allocations allowed) ----------------
__device__ float g_T[L_ * VOCAB_ * D_];            // [l][v][64]
__device__ float g_Q[H_ * L_ * VOCAB_ * D_];       // [h][l][v][64]
__device__ float g_K[H_ * L_ * VOCAB_ * D_];
__device__ float g_V[H_ * L_ * VOCAB_ * D_];
__device__ float g_E[H_ * L_ * VOCAB_ * L_ * VOCAB_]; // [h][k][tk][q][tq]
__device__ float g_VW[H_ * L_ * VOCAB_ * D_];      // [(h*7+k)*6+tk][64]
__device__ float g_Wd[D_ * D_];
__device__ float g_Wf[D_ * NOUT_];
__device__ float g_bf[NOUT_];

// ---------------- prep kernels ----------------
__global__ void k_prep_T(const float* __restrict__ emb, const float* __restrict__ pos,
                         const float* __restrict__ in_w, const float* __restrict__ in_b) {
    int lv = blockIdx.x;           // l*6+v
    int l = lv / 6, v = lv % 6;
    int e = threadIdx.x;
    float acc = in_b[e];
    for (int d = 0; d < 64; d++) acc = fmaf(emb[v * 64 + d], in_w[d * 64 + e], acc);
    acc = fmaf(pos[l], in_w[64 * 64 + e], acc);
    g_T[lv * 64 + e] = acc;
}

__global__ void k_prep_QKV(const float* __restrict__ wq, const float* __restrict__ wk,
                           const float* __restrict__ wv) {
    int lv = blockIdx.x;           // 0..41
    int h = blockIdx.y;            // 0..3
    int which = blockIdx.z;        // 0..2
    int e = threadIdx.x;
    const float* w = (which == 0) ? wq : (which == 1) ? wk : wv;
    float* out = (which == 0) ? g_Q : (which == 1) ? g_K : g_V;
    float acc = 0.f;
    for (int d = 0; d < 64; d++) acc = fmaf(g_T[lv * 64 + d], w[(h * 64 + d) * 64 + e], acc);
    out[(h * 42 + lv) * 64 + e] = acc;
}

__global__ void k_prep_E() {
    int idx = blockIdx.x * blockDim.x + threadIdx.x;
    if (idx >= H_ * 7 * 6 * 7 * 6) return;
    int r = idx;
    int tq = r % 6; r /= 6;
    int q  = r % 7; r /= 7;
    int tk = r % 6; r /= 6;
    int k  = r % 7; r /= 7;
    int h  = r;
    const float* Q = g_Q + ((h * 7 + q) * 6 + tq) * 64;
    const float* K = g_K + ((h * 7 + k) * 6 + tk) * 64;
    float s = 0.f;
    for (int d = 0; d < 64; d++) s = fmaf(Q[d], K[d], s);
    g_E[idx] = __expf(s * 0.125f);
}

__global__ void k_prep_VW(const float* __restrict__ e_wo) {
    int r = blockIdx.x;            // (h*7+k)*6+tk = h*42 + (k*6+tk)
    int h = r / 42;
    int e = threadIdx.x;
    float acc = 0.f;
    for (int d = 0; d < 64; d++) acc = fmaf(g_V[r * 64 + d], e_wo[(h * 64 + d) * 64 + e], acc);
    g_VW[r * 64 + e] = acc;
}

__global__ void k_prep_Wd(const float* __restrict__ d_wv, const float* __restrict__ d_wo) {
    int i = blockIdx.x;            // 0..63
    int j = threadIdx.x;           // 0..63
    float acc = 0.f;
    for (int h = 0; h < 4; h++)
        for (int d = 0; d < 64; d++)
            acc = fmaf(d_wv[(h * 64 + i) * 64 + d], d_wo[(h * 64 + d) * 64 + j], acc);
    g_Wd[i * 64 + j] = acc;
}

__global__ void k_prep_Wf(const float* __restrict__ fc_w, const float* __restrict__ fc_b,
                          const float* __restrict__ d_bo) {
    int tid = threadIdx.x;
    if (tid < 64 * NOUT_) {
        int i = tid / NOUT_, n = tid % NOUT_;
        float acc = 0.f;
        for (int j = 0; j < 64; j++) acc = fmaf(g_Wd[i * 64 + j], fc_w[j * NOUT_ + n], acc);
        g_Wf[i * NOUT_ + n] = acc;
    }
    if (tid < NOUT_) {
        float b = fc_b[tid];
        for (int j = 0; j < 64; j++) b = fmaf(d_bo[j], fc_w[j * NOUT_ + tid], b);
        g_bf[tid] = b;
    }
}

// ---------------- main fused kernel ----------------
// SMEM layout (floats):
//   sE    7056      sVW  10752     sC1  8192      sC2  8192
//   sWf   704       sBf  16        sWco 16*196    sXn  16*64
//   sH1   16*128    sY   16*448
#define SMEM_FLOATS 48288

__global__ __launch_bounds__(512, 1)
void k_main(const int* __restrict__ tokens,
            const float* __restrict__ e_bo,
            const float* __restrict__ g1, const float* __restrict__ b1,
            const float* __restrict__ c1w, const float* __restrict__ c1b,
            const float* __restrict__ c2w, const float* __restrict__ c2b,
            const float* __restrict__ g2, const float* __restrict__ b2,
            float* __restrict__ out, int totalWarps) {
    extern __shared__ float sm[];
    float* sE   = sm;                 // 7056
    float* sVW  = sE + 7056;          // 10752
    float* sC1  = sVW + 10752;        // 8192
    float* sC2  = sC1 + 8192;         // 8192
    float* sWf  = sC2 + 8192;         // 704
    float* sBf  = sWf + 704;          // 16
    float* sWco = sBf + 16;           // 16*196 = 3136
    float* sXn  = sWco + 3136;        // 16*64 = 1024
    float* sH1  = sXn + 1024;         // 16*128 = 2048
    float* sY   = sH1 + 2048;         // 16*448 = 7168

    int tid = threadIdx.x;

    for (int i = tid; i < 7056 / 4;  i += 512) ((float4*)sE)[i]  = ((const float4*)g_E)[i];
    for (int i = tid; i < 10752 / 4; i += 512) ((float4*)sVW)[i] = ((const float4*)g_VW)[i];
    for (int i = tid; i < 8192 / 4;  i += 512) ((float4*)sC1)[i] = ((const float4*)c1w)[i];
    for (int i = tid; i < 8192 / 4;  i += 512) ((float4*)sC2)[i] = ((const float4*)c2w)[i];
    for (int i = tid; i < 704 / 4;   i += 512) ((float4*)sWf)[i] = ((const float4*)g_Wf)[i];
    if (tid < NOUT_) sBf[tid] = g_bf[tid];
    __syncthreads();

    int lane = tid & 31, wid = tid >> 5;

    // loop-invariant params -> registers
    float2 bo2  = ((const float2*)e_bo)[lane];
    float2 g1v  = ((const float2*)g1)[lane];
    float2 b1v  = ((const float2*)b1)[lane];
    float2 g2v  = ((const float2*)g2)[lane];
    float2 b2v  = ((const float2*)b2)[lane];
    float4 c1b4 = ((const float4*)c1b)[lane];
    float2 c2b2 = ((const float2*)c2b)[lane];
    u64 c1b01 = pk2(c1b4.x, c1b4.y), c1b23 = pk2(c1b4.z, c1b4.w);

    float* wco = sWco + wid * 196;
    float* xnW = sXn + wid * 64;
    float* h1W = sH1 + wid * 128;
    float* yW  = sY + wid * 448;

    int gw = blockIdx.x * 16 + wid;
    for (int e = gw; e < BATCH_; e += totalWarps) {
        // one coalesced LDG (lanes 0..6), broadcast via shfl
        int myTok = 0;
        if (lane < 7) myTok = tokens[e * 7 + lane];
        int t[7];
        #pragma unroll
        for (int i = 0; i < 7; i++) t[i] = __shfl_sync(0xffffffffu, myTok, i);

        // --- softmax-over-q weights: wco[q][j], j=(h*7+k) ---
        if (lane < 28) {
            int k = lane % 7;
            const float* eb = sE + (lane * 6 + t[k]) * 42;
            float myw[7];
            float den = 0.f;
            #pragma unroll
            for (int q = 0; q < 7; q++) { float x = eb[q * 6 + t[q]]; myw[q] = x; den += x; }
            float inv = __fdividef(1.f, den);
            #pragma unroll
            for (int q = 0; q < 7; q++) wco[q * 28 + lane] = myw[q] * inv;
        }
        __syncwarp();

        // --- post-attention rows y[q] = bo + sum_j wco[q][j]*VW[j][t_k] ---
        {
            float2 y[7];
            #pragma unroll
            for (int q = 0; q < 7; q++) y[q] = bo2;
            #pragma unroll
            for (int j = 0; j < 28; j++) {
                int k = j % 7;
                float2 v = ((const float2*)(sVW + (j * 6 + t[k]) * 64))[lane];
                #pragma unroll
                for (int q = 0; q < 7; q++) {
                    float w = wco[q * 28 + j];
                    y[q].x = fmaf(w, v.x, y[q].x);
                    y[q].y = fmaf(w, v.y, y[q].y);
                }
            }
            #pragma unroll
            for (int q = 0; q < 7; q++) ((float2*)(yW + q * 64))[lane] = y[q];
        }

        float2 xs = make_float2(0.f, 0.f);
        #pragma unroll 1
        for (int q = 0; q < 7; q++) {
            float2 yq = ((float2*)(yW + q * 64))[lane];
            // LN1
            float s  = yq.x + yq.y;
            float ss = yq.x * yq.x + yq.y * yq.y;
            #pragma unroll
            for (int o = 16; o > 0; o >>= 1) {
                s  += __shfl_xor_sync(0xffffffffu, s, o);
                ss += __shfl_xor_sync(0xffffffffu, ss, o);
            }
            float mean = s * (1.f / 64.f);
            float var  = ss * (1.f / 64.f) - mean * mean;
            float rstd = rsqrtf(var + EPS_);
            float2 xn;
            xn.x = (yq.x - mean) * rstd * g1v.x + b1v.x;
            xn.y = (yq.y - mean) * rstd * g1v.y + b1v.y;
            ((float2*)xnW)[lane] = xn;
            __syncwarp();

            // FFN layer 1: 64 -> 128, lane owns cols [4*lane, 4*lane+3]
            // packed f32x2: weight pairs load free (LDS.128 = 2 x u64 reg pairs),
            // broadcast scalar costs 1 mov.b64 per d.
            u64 a01 = c1b01, a23 = c1b23;
            #pragma unroll 4
            for (int d4 = 0; d4 < 16; d4++) {
                float4 xv = ((const float4*)xnW)[d4];
                const float4* wp = ((const float4*)sC1) + (d4 * 4) * 32 + lane;
                ulonglong2 w; u64 xb;
                xb = bc2(xv.x); w = *(const ulonglong2*)(wp + 0);
                fma2(a01, xb, w.x); fma2(a23, xb, w.y);
                xb = bc2(xv.y); w = *(const ulonglong2*)(wp + 32);
                fma2(a01, xb, w.x); fma2(a23, xb, w.y);
                xb = bc2(xv.z); w = *(const ulonglong2*)(wp + 64);
                fma2(a01, xb, w.x); fma2(a23, xb, w.y);
                xb = bc2(xv.w); w = *(const ulonglong2*)(wp + 96);
                fma2(a01, xb, w.x); fma2(a23, xb, w.y);
            }
            float2 p01 = up2(a01), p23 = up2(a23);
            float4 a;
            a.x = fmaxf(p01.x, 0.f); a.y = fmaxf(p01.y, 0.f);
            a.z = fmaxf(p23.x, 0.f); a.w = fmaxf(p23.y, 0.f);
            ((float4*)h1W)[lane] = a;
            __syncwarp();

            // FFN layer 2: 128 -> 64, lane owns cols [2*lane, 2*lane+1]
            float2 b = c2b2;
            #pragma unroll 4
            for (int d4 = 0; d4 < 32; d4++) {
                float4 hv = ((const float4*)h1W)[d4];
                const float2* wp = ((const float2*)sC2) + (d4 * 4) * 32 + lane;
                float2 w;
                w = wp[0];
                b.x = fmaf(hv.x, w.x, b.x); b.y = fmaf(hv.x, w.y, b.y);
                w = wp[32];
                b.x = fmaf(hv.y, w.x, b.x); b.y = fmaf(hv.y, w.y, b.y);
                w = wp[64];
                b.x = fmaf(hv.z, w.x, b.x); b.y = fmaf(hv.z, w.y, b.y);
                w = wp[96];
                b.x = fmaf(hv.w, w.x, b.x); b.y = fmaf(hv.w, w.y, b.y);
            }
            b.x = fmaxf(b.x, 0.f);
            b.y = fmaxf(b.y, 0.f);
            float2 z = make_float2(xn.x + b.x, xn.y + b.y);

            // LN2 + accumulate token sum (decoder attention == plain sum over L)
            float s2  = z.x + z.y;
            float ss2 = z.x * z.x + z.y * z.y;
            #pragma unroll
            for (int o = 16; o > 0; o >>= 1) {
                s2  += __shfl_xor_sync(0xffffffffu, s2, o);
                ss2 += __shfl_xor_sync(0xffffffffu, ss2, o);
            }
            float mean2 = s2 * (1.f / 64.f);
            float var2  = ss2 * (1.f / 64.f) - mean2 * mean2;
            float rstd2 = rsqrtf(var2 + EPS_);
            xs.x += (z.x - mean2) * rstd2 * g2v.x + b2v.x;
            xs.y += (z.y - mean2) * rstd2 * g2v.y + b2v.y;
            __syncwarp();
        }

        // --- decoder (folded) + fc: out = xs @ Wf + bf ---
        ((float2*)xnW)[lane] = xs;
        __syncwarp();
        if (lane < NOUT_) {
            float o = sBf[lane];
            #pragma unroll 8
            for (int d = 0; d < 64; d++) o = fmaf(xnW[d], sWf[d * NOUT_ + lane], o);
            out[e * NOUT_ + lane] = o;
        }
        __syncwarp();
    }
}

extern "C" void kernel_launch(void* const* d_in, const int* in_sizes, int n_in,
                              void* d_out, int out_size) {
    const int*   tokens = (const int*)d_in[0];
    const float* emb    = (const float*)d_in[1];
    const float* pos    = (const float*)d_in[2];
    // d_in[3] qparam: unused (decoder softmax over singleton axis == 1)
    const float* in_w   = (const float*)d_in[4];
    const float* in_b   = (const float*)d_in[5];
    const float* e_wq   = (const float*)d_in[6];
    const float* e_wk   = (const float*)d_in[7];
    const float* e_wv   = (const float*)d_in[8];
    const float* e_wo   = (const float*)d_in[9];
    const float* e_bo   = (const float*)d_in[10];
    const float* e_g1   = (const float*)d_in[11];
    const float* e_b1   = (const float*)d_in[12];
    const float* e_c1w  = (const float*)d_in[13];
    const float* e_c1b  = (const float*)d_in[14];
    const float* e_c2w  = (const float*)d_in[15];
    const float* e_c2b  = (const float*)d_in[16];
    const float* e_g2   = (const float*)d_in[17];
    const float* e_b2   = (const float*)d_in[18];
    // d_in[19] d_wq, d_in[20] d_wk: unused
    const float* d_wv   = (const float*)d_in[21];
    const float* d_wo   = (const float*)d_in[22];
    const float* d_bo   = (const float*)d_in[23];
    const float* fc_w   = (const float*)d_in[24];
    const float* fc_b   = (const float*)d_in[25];
    float* out = (float*)d_out;

    k_prep_T<<<42, 64>>>(emb, pos, in_w, in_b);
    dim3 gq(42, 4, 3);
    k_prep_QKV<<<gq, 64>>>(e_wq, e_wk, e_wv);
    k_prep_E<<<(7056 + 127) / 128, 128>>>();
    k_prep_VW<<<168, 64>>>(e_wo);
    k_prep_Wd<<<64, 64>>>(d_wv, d_wo);
    k_prep_Wf<<<1, 704>>>(fc_w, fc_b, d_bo);

    int dev = 0;
    cudaGetDevice(&dev);
    int smCount = 148;
    cudaDeviceGetAttribute(&smCount, cudaDevAttrMultiProcessorCount, dev);

    size_t smemBytes = SMEM_FLOATS * sizeof(float);
    cudaFuncSetAttribute(k_main, cudaFuncAttributeMaxDynamicSharedMemorySize, (int)smemBytes);
    k_main<<<smCount, 512, smemBytes>>>(tokens, e_bo, e_g1, e_b1, e_c1w, e_c1b,
                                        e_c2w, e_c2b, e_g2, e_b2, out, smCount * 16);
}

// round 5
// speedup vs baseline: 1.7672x; 1.7672x over previous
#include <cuda_runtime.h>

#define H_ 4
#define D_ 64
#define L_ 7
#define VOCAB_ 6
#define NOUT_ 11
#define BATCH_ 32768
#define EPS_ 1e-5f

using u64 = unsigned long long;

// ---- packed f32x2 helpers (sm_100+) ----
__device__ __forceinline__ u64 pk2(float x, float y) {
    u64 r; asm("mov.b64 %0, {%1, %2};" : "=l"(r) : "f"(x), "f"(y)); return r;
}
__device__ __forceinline__ u64 bc2(float x) {
    u64 r; asm("mov.b64 %0, {%1, %1};" : "=l"(r) : "f"(x)); return r;
}
__device__ __forceinline__ void fma2(u64& a, u64 x, u64 w) {
    asm("fma.rn.f32x2 %0, %1, %2, %0;" : "+l"(a) : "l"(x), "l"(w));
}
__device__ __forceinline__ float2 up2(u64 v) {
    float2 r; asm("mov.b64 {%0, %1}, %2;" : "=f"(r.x), "=f"(r.y) : "l"(v)); return r;
}

// ---------------- scratch (no allocations allowed) ----------------
__device__ float g_E[H_ * L_ * VOCAB_ * L_ * VOCAB_]; // [h][k][tk][q][tq]
__device__ float g_VW[H_ * L_ * VOCAB_ * D_];         // [(h*7+k)*6+tk][64]
__device__ float g_Wf[D_ * NOUT_];
__device__ float g_bf[NOUT_];

// ---------------- single merged prep kernel ----------------
// grid = 9 CTAs x 1024 threads.
//  CTA 0..3 : T -> Q,K (head h=cta)  -> E[h]
//  CTA 4..7 : T -> V   (head h=cta-4)-> VW[h]
//  CTA 8    : Wd (from globals)      -> Wf, bf
__global__ void k_prep(const float* __restrict__ emb, const float* __restrict__ pos,
                       const float* __restrict__ in_w, const float* __restrict__ in_b,
                       const float* __restrict__ e_wq, const float* __restrict__ e_wk,
                       const float* __restrict__ e_wv, const float* __restrict__ e_wo,
                       const float* __restrict__ d_wv, const float* __restrict__ d_wo,
                       const float* __restrict__ d_bo,
                       const float* __restrict__ fc_w, const float* __restrict__ fc_b) {
    extern __shared__ float dyn[];
    int tid = threadIdx.x;
    int cta = blockIdx.x;

    if (cta < 8) {
        float* sT = dyn;          // 2688
        float* sA = dyn + 2688;   // 2688
        float* sB = dyn + 5376;   // 2688
        // T[lv][e]
        for (int i = tid; i < 42 * 64; i += 1024) {
            int lv = i >> 6, e = i & 63;
            int l = lv / 6, v = lv % 6;
            float acc = in_b[e];
            #pragma unroll 8
            for (int d = 0; d < 64; d++) acc = fmaf(emb[v * 64 + d], in_w[d * 64 + e], acc);
            acc = fmaf(pos[l], in_w[64 * 64 + e], acc);
            sT[i] = acc;
        }
        __syncthreads();
        int h = cta & 3;
        if (cta < 4) {
            // Q (sA), K (sB) for head h
            for (int i = tid; i < 2 * 2688; i += 1024) {
                int which = i / 2688, r = i % 2688;
                int lv = r >> 6, e = r & 63;
                const float* w = which ? e_wk : e_wq;
                float acc = 0.f;
                #pragma unroll 8
                for (int d = 0; d < 64; d++) acc = fmaf(sT[lv * 64 + d], w[(h * 64 + d) * 64 + e], acc);
                (which ? sB : sA)[r] = acc;
            }
            __syncthreads();
            // E[h]: 1764 dots
            for (int i = tid; i < 1764; i += 1024) {
                int r = i;
                int tq = r % 6; r /= 6;
                int q  = r % 7; r /= 7;
                int tk = r % 6; r /= 6;
                int k  = r;
                const float* Q = sA + (q * 6 + tq) * 64;
                const float* K = sB + (k * 6 + tk) * 64;
                float s = 0.f;
                #pragma unroll 8
                for (int d = 0; d < 64; d++) s = fmaf(Q[d], K[d], s);
                g_E[h * 1764 + i] = __expf(s * 0.125f);
            }
        } else {
            // V (sA) for head h
            for (int i = tid; i < 2688; i += 1024) {
                int lv = i >> 6, e = i & 63;
                float acc = 0.f;
                #pragma unroll 8
                for (int d = 0; d < 64; d++) acc = fmaf(sT[lv * 64 + d], e_wv[(h * 64 + d) * 64 + e], acc);
                sA[i] = acc;
            }
            __syncthreads();
            // VW[h]
            for (int i = tid; i < 2688; i += 1024) {
                int kv = i >> 6, e = i & 63;
                float acc = 0.f;
                #pragma unroll 8
                for (int d = 0; d < 64; d++) acc = fmaf(sA[kv * 64 + d], e_wo[(h * 64 + d) * 64 + e], acc);
                g_VW[(h * 42 + kv) * 64 + e] = acc;
            }
        }
    } else {
        float* sWd = dyn;  // 4096
        // Wd[r][j] = sum_h sum_d d_wv[h][r][d] * d_wo[h][d][j]
        for (int i = tid; i < 4096; i += 1024) {
            int r = i >> 6, j = i & 63;
            float acc = 0.f;
            for (int hh = 0; hh < 4; hh++)
                #pragma unroll 8
                for (int d = 0; d < 64; d++)
                    acc = fmaf(d_wv[(hh * 64 + r) * 64 + d], d_wo[(hh * 64 + d) * 64 + j], acc);
            sWd[i] = acc;
        }
        __syncthreads();
        for (int i = tid; i < 64 * NOUT_; i += 1024) {
            int r = i / NOUT_, n = i % NOUT_;
            float acc = 0.f;
            #pragma unroll 8
            for (int j = 0; j < 64; j++) acc = fmaf(sWd[r * 64 + j], fc_w[j * NOUT_ + n], acc);
            g_Wf[i] = acc;
        }
        if (tid < NOUT_) {
            float b = fc_b[tid];
            #pragma unroll 8
            for (int j = 0; j < 64; j++) b = fmaf(d_bo[j], fc_w[j * NOUT_ + tid], b);
            g_bf[tid] = b;
        }
    }
}

// ---------------- main fused kernel ----------------
// SMEM (floats): sE 7056 | sVW 10752 | sC1 8192 | sC2 8192 | sWf 704 | sBf 16
//                sWco 16*224 | sXn 16*256 | sH1 16*512
#define SMEM_FLOATS 50784

// FFN pass over M concurrent rows (q = Q0..Q0+M-1).
template<int Q0, int M>
__device__ __forceinline__ void ffn_pass(
    const float2 (&xn)[7], float* xnS, float* h1S,
    const float* sC1, const float* sC2,
    u64 c1b01, u64 c1b23, float2 c2b2,
    float2 g2v, float2 b2v, int lane, float2& xs)
{
    #pragma unroll
    for (int i = 0; i < M; i++)
        ((float2*)(xnS + i * 64))[lane] = xn[Q0 + i];
    __syncwarp();

    // FFN1: 64 -> 128, lane owns cols [4*lane .. 4*lane+3], packed f32x2
    u64 a01[M], a23[M];
    #pragma unroll
    for (int i = 0; i < M; i++) { a01[i] = c1b01; a23[i] = c1b23; }
    #pragma unroll 4
    for (int d4 = 0; d4 < 16; d4++) {
        const float4* wp = ((const float4*)sC1) + (d4 * 4) * 32 + lane;
        ulonglong2 w0 = *(const ulonglong2*)(wp);
        ulonglong2 w1 = *(const ulonglong2*)(wp + 32);
        ulonglong2 w2 = *(const ulonglong2*)(wp + 64);
        ulonglong2 w3 = *(const ulonglong2*)(wp + 96);
        #pragma unroll
        for (int i = 0; i < M; i++) {
            float4 xv = ((const float4*)(xnS + i * 64))[d4];
            u64 xb;
            xb = bc2(xv.x); fma2(a01[i], xb, w0.x); fma2(a23[i], xb, w0.y);
            xb = bc2(xv.y); fma2(a01[i], xb, w1.x); fma2(a23[i], xb, w1.y);
            xb = bc2(xv.z); fma2(a01[i], xb, w2.x); fma2(a23[i], xb, w2.y);
            xb = bc2(xv.w); fma2(a01[i], xb, w3.x); fma2(a23[i], xb, w3.y);
        }
    }
    #pragma unroll
    for (int i = 0; i < M; i++) {
        float2 p01 = up2(a01[i]), p23 = up2(a23[i]);
        float4 a;
        a.x = fmaxf(p01.x, 0.f); a.y = fmaxf(p01.y, 0.f);
        a.z = fmaxf(p23.x, 0.f); a.w = fmaxf(p23.y, 0.f);
        ((float4*)(h1S + i * 128))[lane] = a;
    }
    __syncwarp();

    // FFN2: 128 -> 64, lane owns cols [2*lane, 2*lane+1]
    float2 b[M];
    #pragma unroll
    for (int i = 0; i < M; i++) b[i] = c2b2;
    #pragma unroll 4
    for (int d4 = 0; d4 < 32; d4++) {
        const float2* wp = ((const float2*)sC2) + (d4 * 4) * 32 + lane;
        float2 w0 = wp[0], w1 = wp[32], w2 = wp[64], w3 = wp[96];
        #pragma unroll
        for (int i = 0; i < M; i++) {
            float4 hv = ((const float4*)(h1S + i * 128))[d4];
            b[i].x = fmaf(hv.x, w0.x, b[i].x); b[i].y = fmaf(hv.x, w0.y, b[i].y);
            b[i].x = fmaf(hv.y, w1.x, b[i].x); b[i].y = fmaf(hv.y, w1.y, b[i].y);
            b[i].x = fmaf(hv.z, w2.x, b[i].x); b[i].y = fmaf(hv.z, w2.y, b[i].y);
            b[i].x = fmaf(hv.w, w3.x, b[i].x); b[i].y = fmaf(hv.w, w3.y, b[i].y);
        }
    }

    // residual + LN2 (M concurrent reduction chains) + accumulate token sum
    float s2[M], ss2[M];
    #pragma unroll
    for (int i = 0; i < M; i++) {
        float zx = xn[Q0 + i].x + fmaxf(b[i].x, 0.f);
        float zy = xn[Q0 + i].y + fmaxf(b[i].y, 0.f);
        b[i] = make_float2(zx, zy);
        s2[i] = zx + zy;
        ss2[i] = zx * zx + zy * zy;
    }
    #pragma unroll
    for (int o = 16; o > 0; o >>= 1) {
        #pragma unroll
        for (int i = 0; i < M; i++) {
            s2[i]  += __shfl_xor_sync(0xffffffffu, s2[i], o);
            ss2[i] += __shfl_xor_sync(0xffffffffu, ss2[i], o);
        }
    }
    #pragma unroll
    for (int i = 0; i < M; i++) {
        float mean = s2[i] * (1.f / 64.f);
        float var  = ss2[i] * (1.f / 64.f) - mean * mean;
        float rstd = rsqrtf(var + EPS_);
        xs.x += (b[i].x - mean) * rstd * g2v.x + b2v.x;
        xs.y += (b[i].y - mean) * rstd * g2v.y + b2v.y;
    }
    __syncwarp();
}

__global__ __launch_bounds__(512, 1)
void k_main(const int* __restrict__ tokens,
            const float* __restrict__ e_bo,
            const float* __restrict__ g1, const float* __restrict__ b1,
            const float* __restrict__ c1w, const float* __restrict__ c1b,
            const float* __restrict__ c2w, const float* __restrict__ c2b,
            const float* __restrict__ g2, const float* __restrict__ b2,
            float* __restrict__ out, int totalWarps) {
    extern __shared__ float sm[];
    float* sE   = sm;                 // 7056
    float* sVW  = sE + 7056;          // 10752
    float* sC1  = sVW + 10752;        // 8192
    float* sC2  = sC1 + 8192;         // 8192
    float* sWf  = sC2 + 8192;         // 704
    float* sBf  = sWf + 704;          // 16
    float* sWco = sBf + 16;           // 16*224
    float* sXn  = sWco + 3584;        // 16*256
    float* sH1  = sXn + 4096;         // 16*512

    int tid = threadIdx.x;

    for (int i = tid; i < 7056 / 4;  i += 512) ((float4*)sE)[i]  = ((const float4*)g_E)[i];
    for (int i = tid; i < 10752 / 4; i += 512) ((float4*)sVW)[i] = ((const float4*)g_VW)[i];
    for (int i = tid; i < 8192 / 4;  i += 512) ((float4*)sC1)[i] = ((const float4*)c1w)[i];
    for (int i = tid; i < 8192 / 4;  i += 512) ((float4*)sC2)[i] = ((const float4*)c2w)[i];
    for (int i = tid; i < 704 / 4;   i += 512) ((float4*)sWf)[i] = ((const float4*)g_Wf)[i];
    if (tid < NOUT_) sBf[tid] = g_bf[tid];
    __syncthreads();

    int lane = tid & 31, wid = tid >> 5;

    float2 bo2  = ((const float2*)e_bo)[lane];
    float2 g1v  = ((const float2*)g1)[lane];
    float2 b1v  = ((const float2*)b1)[lane];
    float2 g2v  = ((const float2*)g2)[lane];
    float2 b2v  = ((const float2*)b2)[lane];
    float4 c1b4 = ((const float4*)c1b)[lane];
    float2 c2b2 = ((const float2*)c2b)[lane];
    u64 c1b01 = pk2(c1b4.x, c1b4.y), c1b23 = pk2(c1b4.z, c1b4.w);

    float* wcoW = sWco + wid * 224;   // [j][8] packed
    float* xnW  = sXn + wid * 256;    // 4 rows of 64
    float* h1W  = sH1 + wid * 512;    // 4 rows of 128

    int gw = blockIdx.x * 16 + wid;
    for (int e = gw; e < BATCH_; e += totalWarps) {
        // tokens: one coalesced LDG + shfl broadcast
        int myTok = 0;
        if (lane < 7) myTok = tokens[e * 7 + lane];
        int t[7];
        #pragma unroll
        for (int i = 0; i < 7; i++) t[i] = __shfl_sync(0xffffffffu, myTok, i);

        // softmax-over-q weights, packed wco[j][0..6]
        if (lane < 28) {
            int k = lane % 7;
            const float* eb = sE + (lane * 6 + t[k]) * 42;
            float myw[7];
            float den = 0.f;
            #pragma unroll
            for (int q = 0; q < 7; q++) { float x = eb[q * 6 + t[q]]; myw[q] = x; den += x; }
            float inv = __fdividef(1.f, den);
            float4 wA = make_float4(myw[0] * inv, myw[1] * inv, myw[2] * inv, myw[3] * inv);
            float4 wB = make_float4(myw[4] * inv, myw[5] * inv, myw[6] * inv, 0.f);
            ((float4*)(wcoW + lane * 8))[0] = wA;
            ((float4*)(wcoW + lane * 8))[1] = wB;
        }
        __syncwarp();

        // attention: y[q] = bo + sum_j w[q][j] * VW[j][t_k], y stays in regs
        float2 y[7];
        #pragma unroll
        for (int q = 0; q < 7; q++) y[q] = bo2;
        #pragma unroll
        for (int j = 0; j < 28; j++) {
            int k = j % 7;
            float2 v = ((const float2*)(sVW + (j * 6 + t[k]) * 64))[lane];
            float4 wA = ((const float4*)(wcoW + j * 8))[0];
            float4 wB = ((const float4*)(wcoW + j * 8))[1];
            y[0].x = fmaf(wA.x, v.x, y[0].x); y[0].y = fmaf(wA.x, v.y, y[0].y);
            y[1].x = fmaf(wA.y, v.x, y[1].x); y[1].y = fmaf(wA.y, v.y, y[1].y);
            y[2].x = fmaf(wA.z, v.x, y[2].x); y[2].y = fmaf(wA.z, v.y, y[2].y);
            y[3].x = fmaf(wA.w, v.x, y[3].x); y[3].y = fmaf(wA.w, v.y, y[3].y);
            y[4].x = fmaf(wB.x, v.x, y[4].x); y[4].y = fmaf(wB.x, v.y, y[4].y);
            y[5].x = fmaf(wB.y, v.x, y[5].x); y[5].y = fmaf(wB.y, v.y, y[5].y);
            y[6].x = fmaf(wB.z, v.x, y[6].x); y[6].y = fmaf(wB.z, v.y, y[6].y);
        }

        // LN1 for all 7 q at once: 14 overlapping shfl chains
        float s1[7], ss1[7];
        #pragma unroll
        for (int q = 0; q < 7; q++) {
            s1[q]  = y[q].x + y[q].y;
            ss1[q] = y[q].x * y[q].x + y[q].y * y[q].y;
        }
        #pragma unroll
        for (int o = 16; o > 0; o >>= 1) {
            #pragma unroll
            for (int q = 0; q < 7; q++) {
                s1[q]  += __shfl_xor_sync(0xffffffffu, s1[q], o);
                ss1[q] += __shfl_xor_sync(0xffffffffu, ss1[q], o);
            }
        }
        float2 xn[7];
        #pragma unroll
        for (int q = 0; q < 7; q++) {
            float mean = s1[q] * (1.f / 64.f);
            float var  = ss1[q] * (1.f / 64.f) - mean * mean;
            float rstd = rsqrtf(var + EPS_);
            xn[q].x = (y[q].x - mean) * rstd * g1v.x + b1v.x;
            xn[q].y = (y[q].y - mean) * rstd * g1v.y + b1v.y;
        }

        // FFN + LN2 in two concurrent-row passes
        float2 xs = make_float2(0.f, 0.f);
        ffn_pass<0, 4>(xn, xnW, h1W, sC1, sC2, c1b01, c1b23, c2b2, g2v, b2v, lane, xs);
        ffn_pass<4, 3>(xn, xnW, h1W, sC1, sC2, c1b01, c1b23, c2b2, g2v, b2v, lane, xs);

        // decoder (folded) + fc
        ((float2*)xnW)[lane] = xs;
        __syncwarp();
        if (lane < NOUT_) {
            float o = sBf[lane];
            #pragma unroll 8
            for (int d = 0; d < 64; d++) o = fmaf(xnW[d], sWf[d * NOUT_ + lane], o);
            out[e * NOUT_ + lane] = o;
        }
        __syncwarp();
    }
}

extern "C" void kernel_launch(void* const* d_in, const int* in_sizes, int n_in,
                              void* d_out, int out_size) {
    const int*   tokens = (const int*)d_in[0];
    const float* emb    = (const float*)d_in[1];
    const float* pos    = (const float*)d_in[2];
    // d_in[3] qparam unused (decoder softmax over singleton q axis == 1)
    const float* in_w   = (const float*)d_in[4];
    const float* in_b   = (const float*)d_in[5];
    const float* e_wq   = (const float*)d_in[6];
    const float* e_wk   = (const float*)d_in[7];
    const float* e_wv   = (const float*)d_in[8];
    const float* e_wo   = (const float*)d_in[9];
    const float* e_bo   = (const float*)d_in[10];
    const float* e_g1   = (const float*)d_in[11];
    const float* e_b1   = (const float*)d_in[12];
    const float* e_c1w  = (const float*)d_in[13];
    const float* e_c1b  = (const float*)d_in[14];
    const float* e_c2w  = (const float*)d_in[15];
    const float* e_c2b  = (const float*)d_in[16];
    const float* e_g2   = (const float*)d_in[17];
    const float* e_b2   = (const float*)d_in[18];
    // d_in[19] d_wq, d_in[20] d_wk unused
    const float* d_wv   = (const float*)d_in[21];
    const float* d_wo   = (const float*)d_in[22];
    const float* d_bo   = (const float*)d_in[23];
    const float* fc_w   = (const float*)d_in[24];
    const float* fc_b   = (const float*)d_in[25];
    float* out = (float*)d_out;

    size_t prepSmem = 3 * 2688 * sizeof(float);
    k_prep<<<9, 1024, prepSmem>>>(emb, pos, in_w, in_b, e_wq, e_wk, e_wv, e_wo,
                                  d_wv, d_wo, d_bo, fc_w, fc_b);

    int dev = 0;
    cudaGetDevice(&dev);
    int smCount = 148;
    cudaDeviceGetAttribute(&smCount, cudaDevAttrMultiProcessorCount, dev);

    size_t smemBytes = SMEM_FLOATS * sizeof(float);
    cudaFuncSetAttribute(k_main, cudaFuncAttributeMaxDynamicSharedMemorySize, (int)smemBytes);
    k_main<<<smCount, 512, smemBytes>>>(tokens, e_bo, e_g1, e_b1, e_c1w, e_c1b,
                                        e_c2w, e_c2b, e_g2, e_b2, out, smCount * 16);
}

// round 8
// speedup vs baseline: 1.9807x; 1.1208x over previous
#include <cuda_runtime.h>

#define H_ 4
#define D_ 64
#define L_ 7
#define VOCAB_ 6
#define NOUT_ 11
#define BATCH_ 32768
#define EPS_ 1e-5f

using u64 = unsigned long long;

// ---- packed f32x2 helpers (sm_100+) ----
__device__ __forceinline__ u64 pk2(float x, float y) {
    u64 r; asm("mov.b64 %0, {%1, %2};" : "=l"(r) : "f"(x), "f"(y)); return r;
}
__device__ __forceinline__ u64 bc2(float x) {
    u64 r; asm("mov.b64 %0, {%1, %1};" : "=l"(r) : "f"(x)); return r;
}
__device__ __forceinline__ void fma2(u64& a, u64 x, u64 w) {
    asm("fma.rn.f32x2 %0, %1, %2, %0;" : "+l"(a) : "l"(x), "l"(w));
}
__device__ __forceinline__ float2 up2(u64 v) {
    float2 r; asm("mov.b64 {%0, %1}, %2;" : "=f"(r.x), "=f"(r.y) : "l"(v)); return r;
}

// ---------------- scratch (no allocations allowed) ----------------
__device__ float g_E[H_ * L_ * VOCAB_ * L_ * VOCAB_]; // [h][k][tk][q][tq]
__device__ float g_VW[H_ * L_ * VOCAB_ * D_];         // [(h*7+k)*6+tk][64]
__device__ float g_Wf[D_ * NOUT_];
__device__ float g_bf[NOUT_];

// ---------------- single merged prep kernel ----------------
__global__ void k_prep(const float* __restrict__ emb, const float* __restrict__ pos,
                       const float* __restrict__ in_w, const float* __restrict__ in_b,
                       const float* __restrict__ e_wq, const float* __restrict__ e_wk,
                       const float* __restrict__ e_wv, const float* __restrict__ e_wo,
                       const float* __restrict__ d_wv, const float* __restrict__ d_wo,
                       const float* __restrict__ d_bo,
                       const float* __restrict__ fc_w, const float* __restrict__ fc_b) {
    extern __shared__ float dyn[];
    int tid = threadIdx.x;
    int cta = blockIdx.x;

    if (cta < 8) {
        float* sT = dyn;          // 2688
        float* sA = dyn + 2688;   // 2688
        float* sB = dyn + 5376;   // 2688
        for (int i = tid; i < 42 * 64; i += 1024) {
            int lv = i >> 6, e = i & 63;
            int l = lv / 6, v = lv % 6;
            float acc = in_b[e];
            #pragma unroll 8
            for (int d = 0; d < 64; d++) acc = fmaf(emb[v * 64 + d], in_w[d * 64 + e], acc);
            acc = fmaf(pos[l], in_w[64 * 64 + e], acc);
            sT[i] = acc;
        }
        __syncthreads();
        int h = cta & 3;
        if (cta < 4) {
            for (int i = tid; i < 2 * 2688; i += 1024) {
                int which = i / 2688, r = i % 2688;
                int lv = r >> 6, e = r & 63;
                const float* w = which ? e_wk : e_wq;
                float acc = 0.f;
                #pragma unroll 8
                for (int d = 0; d < 64; d++) acc = fmaf(sT[lv * 64 + d], w[(h * 64 + d) * 64 + e], acc);
                (which ? sB : sA)[r] = acc;
            }
            __syncthreads();
            for (int i = tid; i < 1764; i += 1024) {
                int r = i;
                int tq = r % 6; r /= 6;
                int q  = r % 7; r /= 7;
                int tk = r % 6; r /= 6;
                int k  = r;
                const float* Q = sA + (q * 6 + tq) * 64;
                const float* K = sB + (k * 6 + tk) * 64;
                float s = 0.f;
                #pragma unroll 8
                for (int d = 0; d < 64; d++) s = fmaf(Q[d], K[d], s);
                g_E[h * 1764 + i] = __expf(s * 0.125f);
            }
        } else {
            for (int i = tid; i < 2688; i += 1024) {
                int lv = i >> 6, e = i & 63;
                float acc = 0.f;
                #pragma unroll 8
                for (int d = 0; d < 64; d++) acc = fmaf(sT[lv * 64 + d], e_wv[(h * 64 + d) * 64 + e], acc);
                sA[i] = acc;
            }
            __syncthreads();
            for (int i = tid; i < 2688; i += 1024) {
                int kv = i >> 6, e = i & 63;
                float acc = 0.f;
                #pragma unroll 8
                for (int d = 0; d < 64; d++) acc = fmaf(sA[kv * 64 + d], e_wo[(h * 64 + d) * 64 + e], acc);
                g_VW[(h * 42 + kv) * 64 + e] = acc;
            }
        }
    } else {
        float* sWd = dyn;  // 4096
        for (int i = tid; i < 4096; i += 1024) {
            int r = i >> 6, j = i & 63;
            float acc = 0.f;
            for (int hh = 0; hh < 4; hh++)
                #pragma unroll 8
                for (int d = 0; d < 64; d++)
                    acc = fmaf(d_wv[(hh * 64 + r) * 64 + d], d_wo[(hh * 64 + d) * 64 + j], acc);
            sWd[i] = acc;
        }
        __syncthreads();
        for (int i = tid; i < 64 * NOUT_; i += 1024) {
            int r = i / NOUT_, n = i % NOUT_;
            float acc = 0.f;
            #pragma unroll 8
            for (int j = 0; j < 64; j++) acc = fmaf(sWd[r * 64 + j], fc_w[j * NOUT_ + n], acc);
            g_Wf[i] = acc;
        }
        if (tid < NOUT_) {
            float b = fc_b[tid];
            #pragma unroll 8
            for (int j = 0; j < 64; j++) b = fmaf(d_bo[j], fc_w[j * NOUT_ + tid], b);
            g_bf[tid] = b;
        }
    }
}

// ---------------- main fused kernel ----------------
// 14 warps/CTA, 1 CTA/SM. SMEM (floats):
//   sE 7056 | sVW 10752 | sC1 8192 | sC2 8192 | sWf 704 | sBf 16   (=34912)
//   sWco 14*224 | sXn 14*448 | sH1 14*896
#define NWARP 14
#define NTHR  (NWARP * 32)
#define SMEM_FLOATS (34912 + NWARP * (224 + 448 + 896))

__global__ __launch_bounds__(NTHR, 1)
void k_main(const int* __restrict__ tokens,
            const float* __restrict__ e_bo,
            const float* __restrict__ g1, const float* __restrict__ b1,
            const float* __restrict__ c1w, const float* __restrict__ c1b,
            const float* __restrict__ c2w, const float* __restrict__ c2b,
            const float* __restrict__ g2, const float* __restrict__ b2,
            float* __restrict__ out, int totalWarps) {
    extern __shared__ float sm[];
    float* sE   = sm;                 // 7056
    float* sVW  = sE + 7056;          // 10752
    float* sC1  = sVW + 10752;        // 8192
    float* sC2  = sC1 + 8192;         // 8192
    float* sWf  = sC2 + 8192;         // 704
    float* sBf  = sWf + 704;          // 16
    float* sWco = sBf + 16;           // NWARP*224
    float* sXn  = sWco + NWARP * 224; // NWARP*448
    float* sH1  = sXn + NWARP * 448;  // NWARP*896

    int tid = threadIdx.x;

    for (int i = tid; i < 7056 / 4;  i += NTHR) ((float4*)sE)[i]  = ((const float4*)g_E)[i];
    for (int i = tid; i < 10752 / 4; i += NTHR) ((float4*)sVW)[i] = ((const float4*)g_VW)[i];
    for (int i = tid; i < 8192 / 4;  i += NTHR) ((float4*)sC1)[i] = ((const float4*)c1w)[i];
    for (int i = tid; i < 8192 / 4;  i += NTHR) ((float4*)sC2)[i] = ((const float4*)c2w)[i];
    for (int i = tid; i < 704 / 4;   i += NTHR) ((float4*)sWf)[i] = ((const float4*)g_Wf)[i];
    if (tid < NOUT_) sBf[tid] = g_bf[tid];
    __syncthreads();

    int lane = tid & 31, wid = tid >> 5;

    float2 bo2  = ((const float2*)e_bo)[lane];
    float2 g1v  = ((const float2*)g1)[lane];
    float2 b1v  = ((const float2*)b1)[lane];
    float2 g2v  = ((const float2*)g2)[lane];
    float2 b2v  = ((const float2*)b2)[lane];
    float4 c1b4 = ((const float4*)c1b)[lane];
    float2 c2b2 = ((const float2*)c2b)[lane];
    u64 c1b01 = pk2(c1b4.x, c1b4.y), c1b23 = pk2(c1b4.z, c1b4.w);

    float* wcoW = sWco + wid * 224;   // [j][8]
    float* xnW  = sXn + wid * 448;    // 7 rows of 64
    float* h1W  = sH1 + wid * 896;    // 7 rows of 128

    int gw = blockIdx.x * NWARP + wid;
    for (int e = gw; e < BATCH_; e += totalWarps) {
        // tokens: one coalesced LDG + shfl broadcast
        int myTok = 0;
        if (lane < 7) myTok = tokens[e * 7 + lane];
        int t[7];
        #pragma unroll
        for (int i = 0; i < 7; i++) t[i] = __shfl_sync(0xffffffffu, myTok, i);

        // softmax-over-q weights, packed wco[j][0..6]
        if (lane < 28) {
            int k = lane % 7;
            const float* eb = sE + (lane * 6 + t[k]) * 42;
            float myw[7];
            float den = 0.f;
            #pragma unroll
            for (int q = 0; q < 7; q++) { float x = eb[q * 6 + t[q]]; myw[q] = x; den += x; }
            float inv = __fdividef(1.f, den);
            float4 wA = make_float4(myw[0] * inv, myw[1] * inv, myw[2] * inv, myw[3] * inv);
            float4 wB = make_float4(myw[4] * inv, myw[5] * inv, myw[6] * inv, 0.f);
            ((float4*)(wcoW + lane * 8))[0] = wA;
            ((float4*)(wcoW + lane * 8))[1] = wB;
        }
        __syncwarp();

        // attention: y[q] = bo + sum_j w[q][j] * VW[j][t_k]
        float2 y[7];
        #pragma unroll
        for (int q = 0; q < 7; q++) y[q] = bo2;
        #pragma unroll
        for (int j = 0; j < 28; j++) {
            int k = j % 7;
            float2 v = ((const float2*)(sVW + (j * 6 + t[k]) * 64))[lane];
            float4 wA = ((const float4*)(wcoW + j * 8))[0];
            float4 wB = ((const float4*)(wcoW + j * 8))[1];
            y[0].x = fmaf(wA.x, v.x, y[0].x); y[0].y = fmaf(wA.x, v.y, y[0].y);
            y[1].x = fmaf(wA.y, v.x, y[1].x); y[1].y = fmaf(wA.y, v.y, y[1].y);
            y[2].x = fmaf(wA.z, v.x, y[2].x); y[2].y = fmaf(wA.z, v.y, y[2].y);
            y[3].x = fmaf(wA.w, v.x, y[3].x); y[3].y = fmaf(wA.w, v.y, y[3].y);
            y[4].x = fmaf(wB.x, v.x, y[4].x); y[4].y = fmaf(wB.x, v.y, y[4].y);
            y[5].x = fmaf(wB.y, v.x, y[5].x); y[5].y = fmaf(wB.y, v.y, y[5].y);
            y[6].x = fmaf(wB.z, v.x, y[6].x); y[6].y = fmaf(wB.z, v.y, y[6].y);
        }

        // LN1 for all 7 q at once (14 overlapping shfl chains), store xn to smem
        {
            float s1[7], ss1[7];
            #pragma unroll
            for (int q = 0; q < 7; q++) {
                s1[q]  = y[q].x + y[q].y;
                ss1[q] = y[q].x * y[q].x + y[q].y * y[q].y;
            }
            #pragma unroll
            for (int o = 16; o > 0; o >>= 1) {
                #pragma unroll
                for (int q = 0; q < 7; q++) {
                    s1[q]  += __shfl_xor_sync(0xffffffffu, s1[q], o);
                    ss1[q] += __shfl_xor_sync(0xffffffffu, ss1[q], o);
                }
            }
            #pragma unroll
            for (int q = 0; q < 7; q++) {
                float mean = s1[q] * (1.f / 64.f);
                float var  = ss1[q] * (1.f / 64.f) - mean * mean;
                float rstd = rsqrtf(var + EPS_);
                float2 xn;
                xn.x = (y[q].x - mean) * rstd * g1v.x + b1v.x;
                xn.y = (y[q].y - mean) * rstd * g1v.y + b1v.y;
                ((float2*)(xnW + q * 64))[lane] = xn;
            }
        }
        __syncwarp();

        // ---- FFN1: 64 -> 128, ALL 7 rows in one pass (weights read once) ----
        u64 a01[7], a23[7];
        #pragma unroll
        for (int i = 0; i < 7; i++) { a01[i] = c1b01; a23[i] = c1b23; }
        #pragma unroll 2
        for (int d4 = 0; d4 < 16; d4++) {
            const float4* wp = ((const float4*)sC1) + (d4 * 4) * 32 + lane;
            ulonglong2 w0 = *(const ulonglong2*)(wp);
            ulonglong2 w1 = *(const ulonglong2*)(wp + 32);
            ulonglong2 w2 = *(const ulonglong2*)(wp + 64);
            ulonglong2 w3 = *(const ulonglong2*)(wp + 96);
            #pragma unroll
            for (int i = 0; i < 7; i++) {
                float4 xv = ((const float4*)(xnW + i * 64))[d4];
                u64 xb;
                xb = bc2(xv.x); fma2(a01[i], xb, w0.x); fma2(a23[i], xb, w0.y);
                xb = bc2(xv.y); fma2(a01[i], xb, w1.x); fma2(a23[i], xb, w1.y);
                xb = bc2(xv.z); fma2(a01[i], xb, w2.x); fma2(a23[i], xb, w2.y);
                xb = bc2(xv.w); fma2(a01[i], xb, w3.x); fma2(a23[i], xb, w3.y);
            }
        }
        #pragma unroll
        for (int i = 0; i < 7; i++) {
            float2 p01 = up2(a01[i]), p23 = up2(a23[i]);
            float4 a;
            a.x = fmaxf(p01.x, 0.f); a.y = fmaxf(p01.y, 0.f);
            a.z = fmaxf(p23.x, 0.f); a.w = fmaxf(p23.y, 0.f);
            ((float4*)(h1W + i * 128))[lane] = a;
        }
        __syncwarp();

        // ---- FFN2: 128 -> 64, all 7 rows, weights read once ----
        float2 b[7];
        #pragma unroll
        for (int i = 0; i < 7; i++) b[i] = c2b2;
        #pragma unroll 2
        for (int d4 = 0; d4 < 32; d4++) {
            const float2* wp = ((const float2*)sC2) + (d4 * 4) * 32 + lane;
            float2 w0 = wp[0], w1 = wp[32], w2 = wp[64], w3 = wp[96];
            #pragma unroll
            for (int i = 0; i < 7; i++) {
                float4 hv = ((const float4*)(h1W + i * 128))[d4];
                b[i].x = fmaf(hv.x, w0.x, b[i].x); b[i].y = fmaf(hv.x, w0.y, b[i].y);
                b[i].x = fmaf(hv.y, w1.x, b[i].x); b[i].y = fmaf(hv.y, w1.y, b[i].y);
                b[i].x = fmaf(hv.z, w2.x, b[i].x); b[i].y = fmaf(hv.z, w2.y, b[i].y);
                b[i].x = fmaf(hv.w, w3.x, b[i].x); b[i].y = fmaf(hv.w, w3.y, b[i].y);
            }
        }

        // residual (xn reloaded from smem) + LN2, accumulate token sum
        float2 xs = make_float2(0.f, 0.f);
        {
            float s2[7], ss2[7];
            #pragma unroll
            for (int i = 0; i < 7; i++) {
                float2 xn = ((const float2*)(xnW + i * 64))[lane];
                float zx = xn.x + fmaxf(b[i].x, 0.f);
                float zy = xn.y + fmaxf(b[i].y, 0.f);
                b[i] = make_float2(zx, zy);
                s2[i] = zx + zy;
                ss2[i] = zx * zx + zy * zy;
            }
            #pragma unroll
            for (int o = 16; o > 0; o >>= 1) {
                #pragma unroll
                for (int i = 0; i < 7; i++) {
                    s2[i]  += __shfl_xor_sync(0xffffffffu, s2[i], o);
                    ss2[i] += __shfl_xor_sync(0xffffffffu, ss2[i], o);
                }
            }
            #pragma unroll
            for (int i = 0; i < 7; i++) {
                float mean = s2[i] * (1.f / 64.f);
                float var  = ss2[i] * (1.f / 64.f) - mean * mean;
                float rstd = rsqrtf(var + EPS_);
                xs.x += (b[i].x - mean) * rstd * g2v.x + b2v.x;
                xs.y += (b[i].y - mean) * rstd * g2v.y + b2v.y;
            }
        }
        __syncwarp();

        // decoder (folded) + fc
        ((float2*)xnW)[lane] = xs;
        __syncwarp();
        if (lane < NOUT_) {
            float o = sBf[lane];
            #pragma unroll 8
            for (int d = 0; d < 64; d++) o = fmaf(xnW[d], sWf[d * NOUT_ + lane], o);
            out[e * NOUT_ + lane] = o;
        }
        __syncwarp();
    }
}

extern "C" void kernel_launch(void* const* d_in, const int* in_sizes, int n_in,
                              void* d_out, int out_size) {
    const int*   tokens = (const int*)d_in[0];
    const float* emb    = (const float*)d_in[1];
    const float* pos    = (const float*)d_in[2];
    // d_in[3] qparam unused (decoder softmax over singleton q axis == 1)
    const float* in_w   = (const float*)d_in[4];
    const float* in_b   = (const float*)d_in[5];
    const float* e_wq   = (const float*)d_in[6];
    const float* e_wk   = (const float*)d_in[7];
    const float* e_wv   = (const float*)d_in[8];
    const float* e_wo   = (const float*)d_in[9];
    const float* e_bo   = (const float*)d_in[10];
    const float* e_g1   = (const float*)d_in[11];
    const float* e_b1   = (const float*)d_in[12];
    const float* e_c1w  = (const float*)d_in[13];
    const float* e_c1b  = (const float*)d_in[14];
    const float* e_c2w  = (const float*)d_in[15];
    const float* e_c2b  = (const float*)d_in[16];
    const float* e_g2   = (const float*)d_in[17];
    const float* e_b2   = (const float*)d_in[18];
    // d_in[19] d_wq, d_in[20] d_wk unused
    const float* d_wv   = (const float*)d_in[21];
    const float* d_wo   = (const float*)d_in[22];
    const float* d_bo   = (const float*)d_in[23];
    const float* fc_w   = (const float*)d_in[24];
    const float* fc_b   = (const float*)d_in[25];
    float* out = (float*)d_out;

    size_t prepSmem = 3 * 2688 * sizeof(float);
    k_prep<<<9, 1024, prepSmem>>>(emb, pos, in_w, in_b, e_wq, e_wk, e_wv, e_wo,
                                  d_wv, d_wo, d_bo, fc_w, fc_b);

    int dev = 0;
    cudaGetDevice(&dev);
    int smCount = 148;
    cudaDeviceGetAttribute(&smCount, cudaDevAttrMultiProcessorCount, dev);

    size_t smemBytes = SMEM_FLOATS * sizeof(float);
    cudaFuncSetAttribute(k_main, cudaFuncAttributeMaxDynamicSharedMemorySize, (int)smemBytes);
    k_main<<<smCount, NTHR, smemBytes>>>(tokens, e_bo, e_g1, e_b1, e_c1w, e_c1b,
                                         e_c2w, e_c2b, e_g2, e_b2, out, smCount * NWARP);
}